// round 17
// baseline (speedup 1.0000x reference)
#include <cuda_runtime.h>
#include <cstddef>
#include <cstdint>

#define T_STEPS 2048
#define BATCH   64
#define D_IN    256
#define D_H     256
#define QSTR    0.5f
#define GRP_CTAS 32          // CTAs per barrier group (one b-tile)

// ---------------- scratch (static device global; no allocation) -------------
__device__ unsigned long long g_ctr[4 * 16];           // per-group monotonic ctr

// ---------------------------------------------------------------------------
// packed fp32x2 helpers
// ---------------------------------------------------------------------------
__device__ __forceinline__ unsigned long long pack2(float a, float b) {
    unsigned long long r;
    asm("mov.b64 %0, {%1, %2};" : "=l"(r) : "f"(a), "f"(b));
    return r;
}
__device__ __forceinline__ void unpack2(unsigned long long v, float& a, float& b) {
    asm("mov.b64 {%0, %1}, %2;" : "=f"(a), "=f"(b) : "l"(v));
}
__device__ __forceinline__ void fma2(unsigned long long& d,
                                     unsigned long long a, unsigned long long b) {
    asm("fma.rn.f32x2 %0, %1, %2, %0;" : "+l"(d) : "l"(a), "l"(b));
}
__device__ __forceinline__ float sigmoidf_(float x) {
    return 1.f / (1.f + __expf(-x));
}
__device__ __forceinline__ void red_add_u64(unsigned long long* p) {
    asm volatile("red.global.gpu.add.u64 [%0], %1;" :: "l"(p), "l"(1ull) : "memory");
}
__device__ __forceinline__ unsigned long long ld_vol_u64(const unsigned long long* p) {
    unsigned long long v;
    asm volatile("ld.volatile.global.u64 %0, [%1];" : "=l"(v) : "l"(v = 0, p));
    return v;
}

// correct single-operand form (the above dummy-init trick is invalid; redefine)
__device__ __forceinline__ unsigned long long ld_vol_u64b(const unsigned long long* p) {
    unsigned long long v;
    asm volatile("ld.volatile.global.u64 %0, [%1];" : "=l"(v) : "l"(p));
    return v;
}

// ---------------------------------------------------------------------------
// Fused persistent kernel: per step, compute this CTA's x-projection slice
// (independent of the recurrence -> fills barrier slack), then the h-part.
// 128 CTAs (4 b-tiles x 32 u-tiles), 512 threads.
// warp = (kch 0..7, rh 0..1); lane = (uu 0..7, kcl 0..3); k chunk = 8 wide.
// Weights for BOTH x-part and h-part in registers (wx/wh: 5 gates x 4 pairs).
// One row per acc pass (register pressure). sm_red layout = R12-verified.
// Barrier = R6/R14-verified monotonic counter.
// ---------------------------------------------------------------------------
__global__ void __launch_bounds__(512, 1)
lstm_fused(const float* __restrict__ X,
           const float* __restrict__ Wf, const float* __restrict__ bf,
           const float* __restrict__ Wi, const float* __restrict__ bi,
           const float* __restrict__ Wg, const float* __restrict__ bg,
           const float* __restrict__ Wo, const float* __restrict__ bo,
           const float* __restrict__ Wq, const float* __restrict__ bq,
           float* __restrict__ stacked,   // [T,B,256]
           float* __restrict__ hx_out,    // [B,256]
           float* __restrict__ cx_out)    // [B,256]
{
    extern __shared__ float sm[];
    float* sm_x   = sm;            // [16][264] = 4224
    float* sm_h   = sm + 4224;     // [16][264] = 4224
    float* sm_red = sm + 8448;     // [16 warps][8 uu][41] = 5248

    const int tid  = threadIdx.x;           // 512
    const int warp = tid >> 5;              // 0..15
    const int lane = tid & 31;
    const int b0   = blockIdx.x * 16;       // gridDim.x = 4
    const int u0   = blockIdx.y * 8;        // gridDim.y = 32

    const int uu   = lane & 7;
    const int kcl  = lane >> 3;             // 0..3
    const int kch  = warp & 7;              // 0..7
    const int rh   = warp >> 3;             // 0..1
    const int k0   = (kch * 4 + kcl) * 8;   // 8-k chunk base

    // ---- weights in registers: x-part rows k0.., h-part rows 256+k0.. ----
    unsigned long long wx[5][4], wh[5][4];
    {
        const float* Wp[4] = { Wf, Wi, Wg, Wo };
        #pragma unroll
        for (int g = 0; g < 4; g++)
            #pragma unroll
            for (int kp = 0; kp < 4; kp++) {
                int kx = k0 + 2 * kp;
                wx[g][kp] = pack2(Wp[g][(size_t)kx * 256 + u0 + uu],
                                  Wp[g][(size_t)(kx + 1) * 256 + u0 + uu]);
                int kh = 256 + kx;
                wh[g][kp] = pack2(Wp[g][(size_t)kh * 256 + u0 + uu],
                                  Wp[g][(size_t)(kh + 1) * 256 + u0 + uu]);
            }
        #pragma unroll
        for (int kp = 0; kp < 4; kp++) {
            int kx = k0 + 2 * kp;
            wx[4][kp] = pack2(Wq[(size_t)kx * 8 + uu], Wq[(size_t)(kx + 1) * 8 + uu]);
            int kh = 256 + kx;
            wh[4][kp] = pack2(Wq[(size_t)kh * 8 + uu], Wq[(size_t)(kh + 1) * 8 + uu]);
        }
    }

    // ---- owner mapping: tid < 128 -> one (row, unit) output ----
    const int o_row = tid >> 3;             // 0..15
    const int o_uu  = tid & 7;
    const int ob    = b0 + o_row;
    const int oug   = u0 + o_uu;
    float c = 0.f, h = 0.f;

    unsigned long long* ctr = &g_ctr[blockIdx.x * 16];
    unsigned long long base = 0ull;         // thread0 only

    for (int t = 0; t < T_STEPS; t++) {
        // ================= x-phase (independent of recurrence) =============
        // stage X(t) tile: 16 rows x 256
        {
            const float4* xsrc = (const float4*)(X + ((size_t)t * BATCH + b0) * 256);
            #pragma unroll
            for (int i = 0; i < 2; i++) {
                int idx = tid + i * 512;
                int row = idx >> 6, k4 = idx & 63;
                *(float4*)(sm_x + row * 264 + k4 * 4) = __ldg(xsrc + (size_t)row * 64 + k4);
            }
        }
        __syncthreads();

        // x-dots: one row at a time; reduce over kcl; write sm_red
        #pragma unroll
        for (int j = 0; j < 8; j++) {
            const float* xr = sm_x + (rh * 8 + j) * 264 + k0;
            float4 a = *(const float4*)(xr);
            float4 b = *(const float4*)(xr + 4);
            unsigned long long p0 = pack2(a.x, a.y), p1 = pack2(a.z, a.w);
            unsigned long long p2 = pack2(b.x, b.y), p3 = pack2(b.z, b.w);
            unsigned long long acc[5] = { 0ull, 0ull, 0ull, 0ull, 0ull };
            #pragma unroll
            for (int g = 0; g < 5; g++) {
                fma2(acc[g], p0, wx[g][0]);
                fma2(acc[g], p1, wx[g][1]);
                fma2(acc[g], p2, wx[g][2]);
                fma2(acc[g], p3, wx[g][3]);
            }
            float v[5];
            #pragma unroll
            for (int g = 0; g < 5; g++) {
                float lo, hi;
                unpack2(acc[g], lo, hi);
                v[g] = lo + hi;
            }
            #pragma unroll
            for (int g = 0; g < 5; g++) {
                v[g] += __shfl_xor_sync(0xffffffffu, v[g], 8);
                v[g] += __shfl_xor_sync(0xffffffffu, v[g], 16);
            }
            if (kcl == 0) {
                float* dst = sm_red + (warp * 8 + uu) * 41 + j * 5;
                #pragma unroll
                for (int g = 0; g < 5; g++) dst[g] = v[g];
            }
        }
        __syncthreads();

        // owners: pre-sum x-partials + bias into z regs
        float zF = 0.f, zI = 0.f, zG = 0.f, zO = 0.f, zQ = 0.f;
        if (tid < 128) {
            zF = __ldg(bf + oug);
            zI = __ldg(bi + oug);
            zG = __ldg(bg + oug);
            zO = __ldg(bo + oug);
            zQ = __ldg(bq + o_uu);
            const int rh_o = o_row >> 3;
            const int rr   = o_row & 7;
            #pragma unroll
            for (int w2 = 0; w2 < 8; w2++) {
                const float* src = sm_red + ((rh_o * 8 + w2) * 8 + o_uu) * 41 + rr * 5;
                zF += src[0]; zI += src[1]; zG += src[2]; zO += src[3]; zQ += src[4];
            }
        }

        // ================= wait for h(t-1) of this b-group =================
        if (t > 0) {
            if (tid == 0) {
                unsigned long long target = base + (unsigned long long)t * GRP_CTAS;
                while (ld_vol_u64b(ctr) < target)
                    __nanosleep(16);
            }
        }
        __syncthreads();   // also orders owner sm_red reads before h-phase writes

        // stage h(t-1) tile (zeros at t==0)
        {
            const float4* hsrc = (const float4*)(stacked + ((size_t)(t - 1) * BATCH + b0) * 256);
            #pragma unroll
            for (int i = 0; i < 2; i++) {
                int idx = tid + i * 512;
                int row = idx >> 6, k4 = idx & 63;
                float4 v4;
                if (t == 0) { v4.x = v4.y = v4.z = v4.w = 0.f; }
                else        { v4 = __ldcg(hsrc + (size_t)row * 64 + k4); }
                *(float4*)(sm_h + row * 264 + k4 * 4) = v4;
            }
        }
        __syncthreads();

        // h-dots: one row at a time; reduce; overwrite sm_red
        #pragma unroll
        for (int j = 0; j < 8; j++) {
            const float* hr = sm_h + (rh * 8 + j) * 264 + k0;
            float4 a = *(const float4*)(hr);
            float4 b = *(const float4*)(hr + 4);
            unsigned long long p0 = pack2(a.x, a.y), p1 = pack2(a.z, a.w);
            unsigned long long p2 = pack2(b.x, b.y), p3 = pack2(b.z, b.w);
            unsigned long long acc[5] = { 0ull, 0ull, 0ull, 0ull, 0ull };
            #pragma unroll
            for (int g = 0; g < 5; g++) {
                fma2(acc[g], p0, wh[g][0]);
                fma2(acc[g], p1, wh[g][1]);
                fma2(acc[g], p2, wh[g][2]);
                fma2(acc[g], p3, wh[g][3]);
            }
            float v[5];
            #pragma unroll
            for (int g = 0; g < 5; g++) {
                float lo, hi;
                unpack2(acc[g], lo, hi);
                v[g] = lo + hi;
            }
            #pragma unroll
            for (int g = 0; g < 5; g++) {
                v[g] += __shfl_xor_sync(0xffffffffu, v[g], 8);
                v[g] += __shfl_xor_sync(0xffffffffu, v[g], 16);
            }
            if (kcl == 0) {
                float* dst = sm_red + (warp * 8 + uu) * 41 + j * 5;
                #pragma unroll
                for (int g = 0; g < 5; g++) dst[g] = v[g];
            }
        }
        __syncthreads();

        // ================= owners finalize =================================
        if (tid < 128) {
            const int rh_o = o_row >> 3;
            const int rr   = o_row & 7;
            float aF = zF, aI = zI, aG = zG, aO = zO, aQ = zQ;
            #pragma unroll
            for (int w2 = 0; w2 < 8; w2++) {
                const float* src = sm_red + ((rh_o * 8 + w2) * 8 + o_uu) * 41 + rr * 5;
                aF += src[0]; aI += src[1]; aG += src[2]; aO += src[3]; aQ += src[4];
            }

            float s = tanhf(aQ);
            s += __shfl_xor_sync(0xffffffffu, s, 1);
            s += __shfl_xor_sync(0xffffffffu, s, 2);
            s += __shfl_xor_sync(0xffffffffu, s, 4);
            const float qout = sigmoidf_(s);

            const float f = (1.f - QSTR) * sigmoidf_(aF) + QSTR * qout;
            const float i = sigmoidf_(aI);
            const float g = tanhf(aG);
            const float o = sigmoidf_(aO);

            c = f * c + i * g;
            h = o * tanhf(c);

            __stcg(stacked + ((size_t)t * BATCH + ob) * 256 + oug, h);
            __threadfence();   // h visible before the arrive below
        }
        __syncthreads();

        // ---- arrive (verified R6 protocol) ----
        if (tid == 0) {
            if (t == 0) {
                unsigned long long a = atomicAdd(ctr, 1ull);
                base = (a / GRP_CTAS) * GRP_CTAS;
            } else {
                red_add_u64(ctr);
            }
        }
    }

    if (tid < 128) {
        hx_out[ob * 256 + oug] = h;
        cx_out[ob * 256 + oug] = c;
    }
}

// ---------------------------------------------------------------------------
extern "C" void kernel_launch(void* const* d_in, const int* in_sizes, int n_in,
                              void* d_out, int out_size)
{
    const float* X  = (const float*)d_in[0];
    const float* Wf = (const float*)d_in[1];
    const float* bf = (const float*)d_in[2];
    const float* Wi = (const float*)d_in[3];
    const float* bi = (const float*)d_in[4];
    const float* Wg = (const float*)d_in[5];
    const float* bg = (const float*)d_in[6];
    const float* Wo = (const float*)d_in[7];
    const float* bo = (const float*)d_in[8];
    const float* Wq = (const float*)d_in[9];
    const float* bq = (const float*)d_in[10];

    float* out     = (float*)d_out;
    float* stacked = out;                                  // [T,B,256]
    float* hx_out  = out + (size_t)T_STEPS * BATCH * D_H;  // [B,256]
    float* cx_out  = hx_out + BATCH * D_H;                 // [B,256]

    const int smem_bytes = (4224 + 4224 + 5248) * sizeof(float);  // 54784
    cudaFuncSetAttribute(lstm_fused,
                         cudaFuncAttributeMaxDynamicSharedMemorySize, smem_bytes);
    dim3 g2(4, 32);
    lstm_fused<<<g2, 512, smem_bytes>>>(X, Wf, bf, Wi, bi, Wg, bg, Wo, bo,
                                        Wq, bq, stacked, hx_out, cx_out);
}